// round 13
// baseline (speedup 1.0000x reference)
#include <cuda_runtime.h>
#include <cuda_fp16.h>
#include <cstdint>

// ---------------------------------------------------------------------------
// HGT forward. Node layout: stmt rows [0,100000), func rows [100000,150000).
// Relation transforms folded into GEMM weights. Attention = half-warp-per-dst
// CSR gather + dual-chain online softmax. All GEMMs fp16 m16n8k16, fp32 accum.
// ---------------------------------------------------------------------------
constexpr int kNStmt = 100000;
constexpr int kNFunc = 50000;
constexpr int kNTot  = 150000;
constexpr int kC = 128;
constexpr int kE = 200000;
constexpr int kL = 2;
constexpr int kGridS = (kNStmt + 127) / 128;            // 782
constexpr int kGridF = (kNFunc + 127) / 128;            // 391
constexpr int kGridAll = kGridS + kGridF;               // 1173

// Scratch (device globals: no allocation allowed)
__device__ float  g_x  [(size_t)kNTot * kC];
__device__ float  g_qa [(size_t)kNTot * kC];   // stmt: qa0, func: qa1
__device__ float  g_qa2[(size_t)kNStmt * kC];  // stmt: qa2
__device__ __half g_kh [(size_t)kNTot * kC];
__device__ __half g_vA [(size_t)kNTot * kC];   // stmt: v@M0, func: v@M2
__device__ __half g_vB [(size_t)kNStmt * kC];  // stmt: v@M1
__device__ float  g_agg[(size_t)kNTot * kC];
__device__ __half g_wth[(size_t)22 * 16384];   // fragment-ordered fp16 weights
__device__ float  g_tb [12 * 128];             // transformed biases
__device__ int    g_tmp[500000];               // cnt[250000] then cur[250000]
__device__ int    g_starts[250003];
__device__ int    g_srt[600000];

__device__ __forceinline__ float gelu_t(float u) {
    return 0.5f * u * (1.f + tanhf(0.7978845608028654f * (u + 0.044715f * u * u * u)));
}

#define MMA_F16(c, a, bv0, bv1) \
    asm volatile("mma.sync.aligned.m16n8k16.row.col.f32.f16.f16.f32 " \
        "{%0,%1,%2,%3}, {%4,%5,%6,%7}, {%8,%9}, {%0,%1,%2,%3};" \
        : "+f"((c)[0]), "+f"((c)[1]), "+f"((c)[2]), "+f"((c)[3]) \
        : "r"((a)[0]), "r"((a)[1]), "r"((a)[2]), "r"((a)[3]), "r"(bv0), "r"(bv1))

// ---------------------------------------------------------------------------
// prep_mats: fragment-ordered fp16 weights (22 slots of 16384 halves):
//   0,1 = lin; 2-5 = kw(mi); 6-9 = aw(mi);
//   10+l*6+{0:v0,1:v1,2:v2,3:qa0,4:qa2,5:qa1} (relation-folded)
// fp16 frag (half2 idx i): reg=i&1, lane=(i>>1)&31, ks=(i>>6)&7, nt=i>>9;
//   k0 = ks*16+(lane&3)*2+reg*8 (pair k0,k0+1), n = nt*8+(lane>>2)
// v fold:  out[h,j] = sum_d W[.,h*16+d] * M[h,d,j]
// qa fold: out[h,j] = sum_d W[.,h*16+d] * A[h,j,d]   (scaled by p_rel*0.25)
// ---------------------------------------------------------------------------
__global__ void __launch_bounds__(256) prep_mats(
        const float* __restrict__ lin_w, const float* __restrict__ kw,
        const float* __restrict__ qw, const float* __restrict__ vw,
        const float* __restrict__ aw,
        const float* __restrict__ a_rel, const float* __restrict__ m_rel,
        const float* __restrict__ p_rel,
        const float* __restrict__ qb, const float* __restrict__ vb,
        __half* __restrict__ wth, float* __restrict__ tb)
{
    int b = blockIdx.x, tid = threadIdx.x;
    const int srcT[3] = {0, 0, 1}, dstT[3] = {0, 1, 0};
    __half2* dsth = (__half2*)(wth + (size_t)b * 16384);

    if (b < 10) {
        const float* W = (b < 2) ? lin_w + (size_t)b * 16384
                       : (b < 6) ? kw + (size_t)(b - 2) * 16384
                                 : aw + (size_t)(b - 6) * 16384;
        for (int i = tid; i < 8192; i += 256) {
            int reg = i & 1, lane = (i >> 1) & 31, ks = (i >> 6) & 7, nt = i >> 9;
            int k0 = ks * 16 + (lane & 3) * 2 + reg * 8;
            int n = nt * 8 + (lane >> 2);
            dsth[i] = __floats2half2_rn(__ldg(&W[k0 * 128 + n]),
                                        __ldg(&W[(k0 + 1) * 128 + n]));
        }
        return;
    }
    int c = b - 10, l = c / 6, idx = c % 6;
    int rel = (idx < 3) ? idx : (idx == 3 ? 0 : (idx == 4 ? 2 : 1));
    bool isQA = (idx >= 3);
    const float* W  = isQA ? qw + (size_t)(l * 2 + dstT[rel]) * 16384
                           : vw + (size_t)(l * 2 + srcT[rel]) * 16384;
    const float* T  = (isQA ? a_rel : m_rel) + (size_t)(l * 3 + rel) * 2048;
    const float* Bi = isQA ? qb + (l * 2 + dstT[rel]) * 128
                           : vb + (l * 2 + srcT[rel]) * 128;
    __shared__ float Ts[2048];
    __shared__ float sc[8];
    for (int i = tid; i < 2048; i += 256) Ts[i] = __ldg(&T[i]);
    if (tid < 8) sc[tid] = isQA ? __ldg(&p_rel[(l * 3 + rel) * 8 + tid]) * 0.25f : 1.f;
    __syncthreads();
    for (int i = tid; i < 8192; i += 256) {
        int reg = i & 1, lane = (i >> 1) & 31, ks = (i >> 6) & 7, nt = i >> 9;
        int k0 = ks * 16 + (lane & 3) * 2 + reg * 8;
        int n = nt * 8 + (lane >> 2);
        int h = n >> 4, j = n & 15;
        float s0 = 0.f, s1 = 0.f;
        if (isQA) {
#pragma unroll
            for (int d = 0; d < 16; ++d) {
                float t = Ts[h * 256 + j * 16 + d];
                s0 += __ldg(&W[k0 * 128 + h * 16 + d]) * t;
                s1 += __ldg(&W[(k0 + 1) * 128 + h * 16 + d]) * t;
            }
        } else {
#pragma unroll
            for (int d = 0; d < 16; ++d) {
                float t = Ts[h * 256 + d * 16 + j];
                s0 += __ldg(&W[k0 * 128 + h * 16 + d]) * t;
                s1 += __ldg(&W[(k0 + 1) * 128 + h * 16 + d]) * t;
            }
        }
        dsth[i] = __floats2half2_rn(s0 * sc[h], s1 * sc[h]);
    }
    if (tid < 128) {
        int h = tid >> 4, j = tid & 15;
        float s = 0.f;
        if (isQA) {
#pragma unroll
            for (int d = 0; d < 16; ++d)
                s += __ldg(&Bi[h * 16 + d]) * Ts[h * 256 + j * 16 + d];
        } else {
#pragma unroll
            for (int d = 0; d < 16; ++d)
                s += __ldg(&Bi[h * 16 + d]) * Ts[h * 256 + d * 16 + j];
        }
        tb[c * 128 + tid] = s * sc[h];
    }
}

// ---------------------------------------------------------------------------
// fp16 GEMM mainloop: 512 threads, 16 warps (4M x 4N), warp tile 32x32.
// ---------------------------------------------------------------------------
constexpr int TG_THR = 512;
constexpr int TG_SMEMH = 128 * 136 * 2;   // 34816 B

__device__ __forceinline__ void gemm_tile_h(
        const uint32_t* AshU, const uint32_t* __restrict__ Bfh,
        int warpM, int warpN, int lane, float acc[2][4][4])
{
#pragma unroll
    for (int mt = 0; mt < 2; ++mt)
#pragma unroll
        for (int nt = 0; nt < 4; ++nt)
#pragma unroll
            for (int i = 0; i < 4; ++i) acc[mt][nt][i] = 0.f;
#pragma unroll
    for (int ks = 0; ks < 8; ++ks) {
        uint2 bv[4];
#pragma unroll
        for (int nt = 0; nt < 4; ++nt) {
            int ntA = warpN * 4 + nt;
            bv[nt] = __ldg((const uint2*)Bfh + ((ntA * 8 + ks) * 32 + lane));
        }
        uint32_t a[2][4];
#pragma unroll
        for (int mt = 0; mt < 2; ++mt) {
            int rb = warpM * 32 + mt * 16 + (lane >> 2);
            int cb = ks * 8 + (lane & 3);
            a[mt][0] = AshU[rb * 68 + cb];
            a[mt][1] = AshU[(rb + 8) * 68 + cb];
            a[mt][2] = AshU[rb * 68 + cb + 4];
            a[mt][3] = AshU[(rb + 8) * 68 + cb + 4];
        }
#pragma unroll
        for (int nt = 0; nt < 4; ++nt)
#pragma unroll
            for (int mt = 0; mt < 2; ++mt)
                MMA_F16(acc[mt][nt], a[mt], bv[nt].x, bv[nt].y);
    }
}

// ---------------------------------------------------------------------------
// tgemm1: single-output fp16 GEMM, merged type grid, fp32 output.
// PRE: 1=tanh-gelu, 2=embed(mean+relu).  POST: 1=relu, 2=skip blend.
// ---------------------------------------------------------------------------
template<int PRE, int POST>
__global__ void __launch_bounds__(TG_THR, 2) tgemm1(
        const float* __restrict__ A,
        const int* __restrict__ tok_s, const int* __restrict__ tok_f,
        const float* __restrict__ emb,
        const uint32_t* __restrict__ B0, const uint32_t* __restrict__ B1,
        const float* __restrict__ b0, const float* __restrict__ b1,
        const float* __restrict__ Xold,
        const float* __restrict__ skip0, const float* __restrict__ skip1,
        float* __restrict__ Out)
{
    extern __shared__ float sm[];
    uint32_t* AshU = (uint32_t*)sm;
    __half2* Ash2 = (__half2*)sm;
    int tid = threadIdx.x, wid = tid >> 5, lane = tid & 31;
    int warpM = wid & 3, warpN = wid >> 2;
    int b = blockIdx.x;
    bool tf = (b >= kGridS);
    int rowBase = tf ? (kNStmt + (b - kGridS) * 128) : b * 128;
    int Nend = tf ? kNTot : kNStmt;
    const uint32_t* Bf = tf ? B1 : B0;
    const float* bs = tf ? b1 : b0;

#pragma unroll 2
    for (int p = 0; p < 8; ++p) {
        int idx = p * TG_THR + tid;
        int r = idx >> 5, c4 = idx & 31;
        int n = rowBase + r;
        float4 v = make_float4(0.f, 0.f, 0.f, 0.f);
        if (n < Nend) {
            if (PRE == 2) {
                const int* tok = tf ? tok_f + (size_t)(n - kNStmt) * 16
                                    : tok_s + (size_t)n * 16;
#pragma unroll
                for (int i = 0; i < 16; ++i) {
                    int t = __ldg(&tok[i]);
                    float4 e4 = __ldg((const float4*)(emb + (size_t)t * 128) + c4);
                    v.x += e4.x; v.y += e4.y; v.z += e4.z; v.w += e4.w;
                }
                v.x = fmaxf(v.x * (1.f / 16.f), 0.f);
                v.y = fmaxf(v.y * (1.f / 16.f), 0.f);
                v.z = fmaxf(v.z * (1.f / 16.f), 0.f);
                v.w = fmaxf(v.w * (1.f / 16.f), 0.f);
            } else {
                v = __ldg((const float4*)(A + (size_t)n * 128 + c4 * 4));
                if (PRE == 1) {
                    v.x = gelu_t(v.x); v.y = gelu_t(v.y);
                    v.z = gelu_t(v.z); v.w = gelu_t(v.w);
                }
            }
        }
        Ash2[r * 68 + c4 * 2]     = __floats2half2_rn(v.x, v.y);
        Ash2[r * 68 + c4 * 2 + 1] = __floats2half2_rn(v.z, v.w);
    }
    __syncthreads();

    float gate = 1.f, og = 0.f;
    if (POST == 2) {
        float sv = __ldg(tf ? skip1 : skip0);
        gate = 1.f / (1.f + expf(-sv));
        og = 1.f - gate;
    }

    float acc[2][4][4];
    gemm_tile_h(AshU, Bf, warpM, warpN, lane, acc);

    int g = lane >> 2, t2 = (lane & 3) * 2;
#pragma unroll
    for (int mt = 0; mt < 2; ++mt) {
        int r0 = rowBase + warpM * 32 + mt * 16 + g;
#pragma unroll
        for (int nt = 0; nt < 4; ++nt) {
            int col = warpN * 32 + nt * 8 + t2;
            float bb0 = __ldg(&bs[col]), bb1 = __ldg(&bs[col + 1]);
            float o0 = acc[mt][nt][0] + bb0, o1 = acc[mt][nt][1] + bb1;
            float o2 = acc[mt][nt][2] + bb0, o3 = acc[mt][nt][3] + bb1;
            if (POST == 1) {
                o0 = fmaxf(o0, 0.f); o1 = fmaxf(o1, 0.f);
                o2 = fmaxf(o2, 0.f); o3 = fmaxf(o3, 0.f);
            }
            if (POST == 2) {
                if (r0 < Nend) {
                    float2 x = *(const float2*)(Xold + (size_t)r0 * 128 + col);
                    o0 = gate * o0 + og * x.x; o1 = gate * o1 + og * x.y;
                }
                if (r0 + 8 < Nend) {
                    float2 x = *(const float2*)(Xold + (size_t)(r0 + 8) * 128 + col);
                    o2 = gate * o2 + og * x.x; o3 = gate * o3 + og * x.y;
                }
            }
            if (r0 < Nend)
                *(float2*)(Out + (size_t)r0 * 128 + col) = make_float2(o0, o1);
            if (r0 + 8 < Nend)
                *(float2*)(Out + (size_t)(r0 + 8) * 128 + col) = make_float2(o2, o3);
        }
    }
}

// ---------------------------------------------------------------------------
// tgemm_kqv: 5 outputs. j: 0=k(h16) 1=vA(h16) 2=vB(h16,stmt) 3=qa(f32) 4=qa2(f32,stmt)
// ---------------------------------------------------------------------------
struct KqvP {
    const uint32_t* B[2][5];
    const float*    bs[2][5];
};

__global__ void __launch_bounds__(TG_THR, 2) tgemm_kqv(
        const float* __restrict__ A, KqvP P,
        __half* __restrict__ Ok, __half* __restrict__ OvA, __half* __restrict__ OvB,
        float* __restrict__ Oqa, float* __restrict__ Oqa2)
{
    extern __shared__ float sm[];
    uint32_t* AshU = (uint32_t*)sm;
    __half2* Ash2 = (__half2*)sm;
    int tid = threadIdx.x, wid = tid >> 5, lane = tid & 31;
    int warpM = wid & 3, warpN = wid >> 2;
    int b = blockIdx.x;
    bool tf = (b >= kGridS);
    int rowBase = tf ? (kNStmt + (b - kGridS) * 128) : b * 128;
    int Nend = tf ? kNTot : kNStmt;
    int ti = tf ? 1 : 0;

#pragma unroll 4
    for (int p = 0; p < 8; ++p) {
        int idx = p * TG_THR + tid;
        int r = idx >> 5, c4 = idx & 31;
        int n = rowBase + r;
        float4 v = make_float4(0.f, 0.f, 0.f, 0.f);
        if (n < Nend) v = __ldg((const float4*)(A + (size_t)n * 128 + c4 * 4));
        Ash2[r * 68 + c4 * 2]     = __floats2half2_rn(v.x, v.y);
        Ash2[r * 68 + c4 * 2 + 1] = __floats2half2_rn(v.z, v.w);
    }
    __syncthreads();

    int g = lane >> 2, t2 = (lane & 3) * 2;
#pragma unroll
    for (int j = 0; j < 5; ++j) {
        if (tf && (j == 2 || j == 4)) continue;
        float acc[2][4][4];
        gemm_tile_h(AshU, P.B[ti][j], warpM, warpN, lane, acc);
        const float* bs = P.bs[ti][j];
#pragma unroll
        for (int mt = 0; mt < 2; ++mt) {
            int r0 = rowBase + warpM * 32 + mt * 16 + g;
#pragma unroll
            for (int nt = 0; nt < 4; ++nt) {
                int col = warpN * 32 + nt * 8 + t2;
                float bb0 = __ldg(&bs[col]), bb1 = __ldg(&bs[col + 1]);
                float o0 = acc[mt][nt][0] + bb0, o1 = acc[mt][nt][1] + bb1;
                float o2 = acc[mt][nt][2] + bb0, o3 = acc[mt][nt][3] + bb1;
                if (j < 3) {
                    __half* Oh = (j == 0) ? Ok : (j == 1) ? OvA : OvB;
                    if (r0 < Nend)
                        *(__half2*)(Oh + (size_t)r0 * 128 + col) = __floats2half2_rn(o0, o1);
                    if (r0 + 8 < Nend)
                        *(__half2*)(Oh + (size_t)(r0 + 8) * 128 + col) = __floats2half2_rn(o2, o3);
                } else {
                    float* Of = (j == 3) ? Oqa : Oqa2;
                    if (r0 < Nend)
                        *(float2*)(Of + (size_t)r0 * 128 + col) = make_float2(o0, o1);
                    if (r0 + 8 < Nend)
                        *(float2*)(Of + (size_t)(r0 + 8) * 128 + col) = make_float2(o2, o3);
                }
            }
        }
    }
}

// ---------------------------------------------------------------------------
// CSR build
// ---------------------------------------------------------------------------
__global__ void zero_int(int* __restrict__ p, int n) {
    int i = blockIdx.x * 256 + threadIdx.x;
    if (i < n) p[i] = 0;
}

__global__ void hist3(const int* __restrict__ d0, const int* __restrict__ d1,
                      const int* __restrict__ d2, int* __restrict__ cnt) {
    int r = blockIdx.y;
    const int* dst = (r == 0) ? d0 : (r == 1) ? d1 : d2;
    int off = (r == 0) ? 0 : (r == 1) ? kNStmt : kNStmt + kNFunc;
    int i = blockIdx.x * 256 + threadIdx.x;
    if (i < kE) atomicAdd(&cnt[off + __ldg(&dst[i])], 1);
}

__global__ void __launch_bounds__(1024) exscan3(const int* __restrict__ cnt,
                                                int* __restrict__ starts) {
    __shared__ int wsum[32];
    __shared__ int carry_s;
    const int cntOff[3] = {0, kNStmt, kNStmt + kNFunc};
    const int stOff[3]  = {0, kNStmt + 1, kNStmt + kNFunc + 2};
    const int ns[3]     = {kNStmt, kNFunc, kNStmt};
    int r = blockIdx.x;
    const int* c = cnt + cntOff[r];
    int* st = starts + stOff[r];
    int n = ns[r];
    int tid = threadIdx.x, lane = tid & 31, w = tid >> 5;
    if (tid == 0) carry_s = 0;
    __syncthreads();
    for (int base = 0; base < n; base += 1024) {
        int i = base + tid;
        int v = (i < n) ? c[i] : 0;
        int x = v;
#pragma unroll
        for (int o = 1; o < 32; o <<= 1) {
            int t = __shfl_up_sync(0xffffffffu, x, o);
            if (lane >= o) x += t;
        }
        if (lane == 31) wsum[w] = x;
        __syncthreads();
        if (w == 0) {
            int y = wsum[lane];
#pragma unroll
            for (int o = 1; o < 32; o <<= 1) {
                int t = __shfl_up_sync(0xffffffffu, y, o);
                if (lane >= o) y += t;
            }
            wsum[lane] = y;
        }
        __syncthreads();
        int incl = x + (w > 0 ? wsum[w - 1] : 0);
        int carry = carry_s;
        if (i < n) st[i] = carry + incl - v;
        __syncthreads();
        if (tid == 0) carry_s = carry + wsum[31];
        __syncthreads();
    }
    if (tid == 0) st[n] = carry_s;
}

__global__ void scat3(const int* __restrict__ s0, const int* __restrict__ d0,
                      const int* __restrict__ s1, const int* __restrict__ d1,
                      const int* __restrict__ s2, const int* __restrict__ d2,
                      const int* __restrict__ starts, int* __restrict__ cur,
                      int* __restrict__ out) {
    int r = blockIdx.y;
    const int* src = (r == 0) ? s0 : (r == 1) ? s1 : s2;
    const int* dst = (r == 0) ? d0 : (r == 1) ? d1 : d2;
    int cOff = (r == 0) ? 0 : (r == 1) ? kNStmt : kNStmt + kNFunc;
    int sOff = (r == 0) ? 0 : (r == 1) ? kNStmt + 1 : kNStmt + kNFunc + 2;
    int i = blockIdx.x * 256 + threadIdx.x;
    if (i < kE) {
        int d = __ldg(&dst[i]);
        int pos = __ldg(&starts[sOff + d]) + atomicAdd(&cur[cOff + d], 1);
        out[(size_t)r * kE + pos] = __ldg(&src[i]);
    }
}

// ---------------------------------------------------------------------------
// Attention: half-warp per dst (16 lanes x uint4 = full 256B row), dual-chain
// interleaved online softmax (rel0 + rel2 for stmt dsts). Head logit via one
// shfl_xor(1) within the lane pair; shuffles masked per half-warp.
// ---------------------------------------------------------------------------
__device__ __forceinline__ void attn_step(
        uint4 uk, uint4 uv, const float* q8, unsigned hmask,
        float& m, float& s, float* acc)
{
    float2 k0 = __half22float2(*(__half2*)&uk.x);
    float2 k1 = __half22float2(*(__half2*)&uk.y);
    float2 k2 = __half22float2(*(__half2*)&uk.z);
    float2 k3 = __half22float2(*(__half2*)&uk.w);
    float partial = q8[0] * k0.x + q8[1] * k0.y + q8[2] * k1.x + q8[3] * k1.y
                  + q8[4] * k2.x + q8[5] * k2.y + q8[6] * k3.x + q8[7] * k3.y;
    float lg = partial + __shfl_xor_sync(hmask, partial, 1);
    float nm = fmaxf(m, lg);
    float corr = __expf(m - nm);
    float p = __expf(lg - nm);
    s = s * corr + p;
    float2 v0 = __half22float2(*(__half2*)&uv.x);
    float2 v1 = __half22float2(*(__half2*)&uv.y);
    float2 v2 = __half22float2(*(__half2*)&uv.z);
    float2 v3 = __half22float2(*(__half2*)&uv.w);
    acc[0] = acc[0] * corr + p * v0.x;
    acc[1] = acc[1] * corr + p * v0.y;
    acc[2] = acc[2] * corr + p * v1.x;
    acc[3] = acc[3] * corr + p * v1.y;
    acc[4] = acc[4] * corr + p * v2.x;
    acc[5] = acc[5] * corr + p * v2.y;
    acc[6] = acc[6] * corr + p * v3.x;
    acc[7] = acc[7] * corr + p * v3.y;
    m = nm;
}

constexpr int kBlkS = kNStmt / 16;   // 6250 blocks, 16 dst each
constexpr int kBlkF = kNFunc / 16;   // 3125

__global__ void __launch_bounds__(256) attn_all(
        const float* __restrict__ qa, const float* __restrict__ qa2,
        const __half* __restrict__ kh, const __half* __restrict__ vA,
        const __half* __restrict__ vB,
        const int* __restrict__ st, const int* __restrict__ srt,
        float* __restrict__ agg)
{
    int tid = threadIdx.x;
    int hwIdx = tid >> 4;          // half-warp index in block: 0..15
    int l16 = tid & 15;            // lane within half-warp
    unsigned hmask = 0xFFFFu << ((tid & 31) & 16);
    int b = blockIdx.x;

    if (b < kBlkS) {
        int dn = b * 16 + hwIdx;
        // q rows: 8 floats per lane for each relation
        float q0[8], q2[8];
        {
            const float4* qp = (const float4*)(qa + (size_t)dn * 128) + l16 * 2;
            float4 a = __ldg(&qp[0]), bq = __ldg(&qp[1]);
            q0[0]=a.x; q0[1]=a.y; q0[2]=a.z; q0[3]=a.w;
            q0[4]=bq.x; q0[5]=bq.y; q0[6]=bq.z; q0[7]=bq.w;
            const float4* qp2 = (const float4*)(qa2 + (size_t)dn * 128) + l16 * 2;
            float4 c = __ldg(&qp2[0]), d = __ldg(&qp2[1]);
            q2[0]=c.x; q2[1]=c.y; q2[2]=c.z; q2[3]=c.w;
            q2[4]=d.x; q2[5]=d.y; q2[6]=d.z; q2[7]=d.w;
        }
        int eA = __ldg(&st[dn]), eA1 = __ldg(&st[dn + 1]);
        const int* st2 = st + (kNStmt + kNFunc + 2);
        int eB = __ldg(&st2[dn]), eB1 = __ldg(&st2[dn + 1]);
        const int* srB = srt + 2 * kE;
        const __half* khF = kh + (size_t)kNStmt * 128;
        const __half* vAF = vA + (size_t)kNStmt * 128;

        float mA = -INFINITY, sA = 0.f, accA[8] = {0,0,0,0,0,0,0,0};
        float mB = -INFINITY, sB = 0.f, accB[8] = {0,0,0,0,0,0,0,0};
        while (eA < eA1 || eB < eB1) {
            bool a = eA < eA1, bb = eB < eB1;
            uint4 ka, va, kb2, vb2;
            if (a) {
                int s0 = __ldg(&srt[eA]);
                ka = __ldg((const uint4*)(kh + (size_t)s0 * 128) + l16);
                va = __ldg((const uint4*)(vA + (size_t)s0 * 128) + l16);
            }
            if (bb) {
                int s1 = __ldg(&srB[eB]);
                kb2 = __ldg((const uint4*)(khF + (size_t)s1 * 128) + l16);
                vb2 = __ldg((const uint4*)(vAF + (size_t)s1 * 128) + l16);
            }
            if (a)  { attn_step(ka, va, q0, hmask, mA, sA, accA); ++eA; }
            if (bb) { attn_step(kb2, vb2, q2, hmask, mB, sB, accB); ++eB; }
        }
        float invA = 1.f / (sA + 1e-16f), invB = 1.f / (sB + 1e-16f);
        float4* op = (float4*)(agg + (size_t)dn * 128) + l16 * 2;
        op[0] = make_float4(accA[0] * invA + accB[0] * invB,
                            accA[1] * invA + accB[1] * invB,
                            accA[2] * invA + accB[2] * invB,
                            accA[3] * invA + accB[3] * invB);
        op[1] = make_float4(accA[4] * invA + accB[4] * invB,
                            accA[5] * invA + accB[5] * invB,
                            accA[6] * invA + accB[6] * invB,
                            accA[7] * invA + accB[7] * invB);
    } else {
        int dn = (b - kBlkS) * 16 + hwIdx;
        float q1[8];
        {
            const float4* qp = (const float4*)(qa + (size_t)(kNStmt + dn) * 128) + l16 * 2;
            float4 a = __ldg(&qp[0]), bq = __ldg(&qp[1]);
            q1[0]=a.x; q1[1]=a.y; q1[2]=a.z; q1[3]=a.w;
            q1[4]=bq.x; q1[5]=bq.y; q1[6]=bq.z; q1[7]=bq.w;
        }
        const int* st1 = st + (kNStmt + 1);
        int e = __ldg(&st1[dn]), e1 = __ldg(&st1[dn + 1]);
        const int* sr1 = srt + kE;
        float m = -INFINITY, s = 0.f, acc[8] = {0,0,0,0,0,0,0,0};
        while (e < e1) {
            int s0 = __ldg(&sr1[e]);
            uint4 ka = __ldg((const uint4*)(kh + (size_t)s0 * 128) + l16);
            uint4 va = __ldg((const uint4*)(vB + (size_t)s0 * 128) + l16);
            attn_step(ka, va, q1, hmask, m, s, acc);
            ++e;
        }
        float inv = 1.f / (s + 1e-16f);
        float4* op = (float4*)(agg + (size_t)(kNStmt + dn) * 128) + l16 * 2;
        op[0] = make_float4(acc[0] * inv, acc[1] * inv, acc[2] * inv, acc[3] * inv);
        op[1] = make_float4(acc[4] * inv, acc[5] * inv, acc[6] * inv, acc[7] * inv);
    }
}

// ---------------------------------------------------------------------------
// Orchestration
// ---------------------------------------------------------------------------
extern "C" void kernel_launch(void* const* d_in, const int* in_sizes, int n_in,
                              void* d_out, int out_size) {
    const int* tok_s = (const int*)d_in[0];
    const int* tok_f = (const int*)d_in[1];
    const int* e0s = (const int*)d_in[2], *e0d = (const int*)d_in[3];
    const int* e1s = (const int*)d_in[4], *e1d = (const int*)d_in[5];
    const int* e2s = (const int*)d_in[6], *e2d = (const int*)d_in[7];
    const float* emb   = (const float*)d_in[8];
    const float* lin_w = (const float*)d_in[9];
    const float* lin_b = (const float*)d_in[10];
    const float* kw = (const float*)d_in[11];
    const float* kb = (const float*)d_in[12];
    const float* qw = (const float*)d_in[13];
    const float* qb = (const float*)d_in[14];
    const float* vw = (const float*)d_in[15];
    const float* vb = (const float*)d_in[16];
    const float* aw = (const float*)d_in[17];
    const float* ab = (const float*)d_in[18];
    const float* skip  = (const float*)d_in[19];
    const float* a_rel = (const float*)d_in[20];
    const float* m_rel = (const float*)d_in[21];
    const float* p_rel = (const float*)d_in[22];
    float* out = (float*)d_out;

    float *px, *pqa, *pqa2, *pagg, *ptb;
    __half *pkh, *pvA, *pvB, *pwth;
    int *ptmp, *pst, *psrt;
    cudaGetSymbolAddress((void**)&px,   g_x);
    cudaGetSymbolAddress((void**)&pqa,  g_qa);
    cudaGetSymbolAddress((void**)&pqa2, g_qa2);
    cudaGetSymbolAddress((void**)&pkh,  g_kh);
    cudaGetSymbolAddress((void**)&pvA,  g_vA);
    cudaGetSymbolAddress((void**)&pvB,  g_vB);
    cudaGetSymbolAddress((void**)&pagg, g_agg);
    cudaGetSymbolAddress((void**)&pwth, g_wth);
    cudaGetSymbolAddress((void**)&ptb,  g_tb);
    cudaGetSymbolAddress((void**)&ptmp, g_tmp);
    cudaGetSymbolAddress((void**)&pst,  g_starts);
    cudaGetSymbolAddress((void**)&psrt, g_srt);

    cudaFuncSetAttribute(tgemm1<2,1>, cudaFuncAttributeMaxDynamicSharedMemorySize, TG_SMEMH);
    cudaFuncSetAttribute(tgemm1<1,2>, cudaFuncAttributeMaxDynamicSharedMemorySize, TG_SMEMH);
    cudaFuncSetAttribute(tgemm_kqv, cudaFuncAttributeMaxDynamicSharedMemorySize, TG_SMEMH);

    int egrid = (kE + 255) / 256;

    // CSR build
    zero_int<<<(500000 + 255) / 256, 256>>>(ptmp, 500000);
    hist3<<<dim3(egrid, 3), 256>>>(e0d, e1d, e2d, ptmp);
    exscan3<<<3, 1024>>>(ptmp, pst);
    scat3<<<dim3(egrid, 3), 256>>>(e0s, e0d, e1s, e1d, e2s, e2d,
                                   pst, ptmp + 250000, psrt);

    // Weight prep, then input linear with fused embed
    prep_mats<<<22, 256>>>(lin_w, kw, qw, vw, aw, a_rel, m_rel, p_rel, qb, vb,
                           pwth, ptb);

    const uint32_t* W = (const uint32_t*)pwth;   // 8192 uint32 per matrix
    tgemm1<2,1><<<kGridAll, TG_THR, TG_SMEMH>>>(
        nullptr, tok_s, tok_f, emb,
        W, W + 8192, lin_b, lin_b + 128,
        nullptr, nullptr, nullptr, px);

    for (int l = 0; l < kL; ++l) {
        int m0 = l * 2, m1 = l * 2 + 1;
        size_t fs = 10 + (size_t)l * 6;

        KqvP P;
        P.B[0][0] = W + (size_t)(2 + m0) * 8192;
        P.B[0][1] = W + (fs + 0) * 8192;
        P.B[0][2] = W + (fs + 1) * 8192;
        P.B[0][3] = W + (fs + 3) * 8192;
        P.B[0][4] = W + (fs + 4) * 8192;
        P.bs[0][0] = kb + m0 * 128;
        P.bs[0][1] = ptb + (l * 6 + 0) * 128;
        P.bs[0][2] = ptb + (l * 6 + 1) * 128;
        P.bs[0][3] = ptb + (l * 6 + 3) * 128;
        P.bs[0][4] = ptb + (l * 6 + 4) * 128;
        P.B[1][0] = W + (size_t)(2 + m1) * 8192;
        P.B[1][1] = W + (fs + 2) * 8192;
        P.B[1][2] = nullptr;
        P.B[1][3] = W + (fs + 5) * 8192;
        P.B[1][4] = nullptr;
        P.bs[1][0] = kb + m1 * 128;
        P.bs[1][1] = ptb + (l * 6 + 2) * 128;
        P.bs[1][2] = nullptr;
        P.bs[1][3] = ptb + (l * 6 + 5) * 128;
        P.bs[1][4] = nullptr;

        tgemm_kqv<<<kGridAll, TG_THR, TG_SMEMH>>>(px, P, pkh, pvA, pvB, pqa, pqa2);

        attn_all<<<kBlkS + kBlkF, 256>>>(pqa, pqa2, pkh, pvA, pvB,
                                         pst, psrt, pagg);

        float* dst = (l == kL - 1) ? out : px;
        tgemm1<1,2><<<kGridAll, TG_THR, TG_SMEMH>>>(
            pagg, nullptr, nullptr, nullptr,
            W + (size_t)(6 + m0) * 8192, W + (size_t)(6 + m1) * 8192,
            ab + m0 * 128, ab + m1 * 128,
            px, skip + m0, skip + m1, dst);
    }
}

// round 15
// speedup vs baseline: 1.3634x; 1.3634x over previous
#include <cuda_runtime.h>
#include <cuda_fp16.h>
#include <cstdint>

// ---------------------------------------------------------------------------
// HGT forward. Node layout: stmt rows [0,100000), func rows [100000,150000).
// Relation transforms folded into GEMM weights. Attention = warp-per-dst CSR
// gather + online softmax, one warp per (dst, relation) chain. All GEMMs
// fp16 m16n8k16, fp32 accumulate.
// ---------------------------------------------------------------------------
constexpr int kNStmt = 100000;
constexpr int kNFunc = 50000;
constexpr int kNTot  = 150000;
constexpr int kC = 128;
constexpr int kE = 200000;
constexpr int kL = 2;
constexpr int kGridS = (kNStmt + 127) / 128;            // 782
constexpr int kGridF = (kNFunc + 127) / 128;            // 391
constexpr int kGridAll = kGridS + kGridF;               // 1173

// Scratch (device globals: no allocation allowed)
__device__ float  g_x  [(size_t)kNTot * kC];
__device__ float  g_qa [(size_t)kNTot * kC];   // stmt: qa0, func: qa1
__device__ float  g_qa2[(size_t)kNStmt * kC];  // stmt: qa2
__device__ __half g_kh [(size_t)kNTot * kC];
__device__ __half g_vA [(size_t)kNTot * kC];   // stmt: v@M0, func: v@M2
__device__ __half g_vB [(size_t)kNStmt * kC];  // stmt: v@M1
__device__ float  g_agg [(size_t)kNTot * kC];  // rel0 (stmt) + rel1 (func)
__device__ float  g_agg2[(size_t)kNStmt * kC]; // rel2 (stmt)
__device__ __half g_wth[(size_t)22 * 16384];   // fragment-ordered fp16 weights
__device__ float  g_tb [12 * 128];             // transformed biases
__device__ int    g_tmp[500000];               // cnt[250000] then cur[250000]
__device__ int    g_starts[250003];
__device__ int    g_srt[600000];

__device__ __forceinline__ float gelu_t(float u) {
    return 0.5f * u * (1.f + tanhf(0.7978845608028654f * (u + 0.044715f * u * u * u)));
}

#define MMA_F16(c, a, bv0, bv1) \
    asm volatile("mma.sync.aligned.m16n8k16.row.col.f32.f16.f16.f32 " \
        "{%0,%1,%2,%3}, {%4,%5,%6,%7}, {%8,%9}, {%0,%1,%2,%3};" \
        : "+f"((c)[0]), "+f"((c)[1]), "+f"((c)[2]), "+f"((c)[3]) \
        : "r"((a)[0]), "r"((a)[1]), "r"((a)[2]), "r"((a)[3]), "r"(bv0), "r"(bv1))

// ---------------------------------------------------------------------------
// prep_mats: fragment-ordered fp16 weights (22 slots of 16384 halves):
//   0,1 = lin; 2-5 = kw(mi); 6-9 = aw(mi);
//   10+l*6+{0:v0,1:v1,2:v2,3:qa0,4:qa2,5:qa1} (relation-folded)
// fp16 frag (half2 idx i): reg=i&1, lane=(i>>1)&31, ks=(i>>6)&7, nt=i>>9;
//   k0 = ks*16+(lane&3)*2+reg*8 (pair k0,k0+1), n = nt*8+(lane>>2)
// v fold:  out[h,j] = sum_d W[.,h*16+d] * M[h,d,j]
// qa fold: out[h,j] = sum_d W[.,h*16+d] * A[h,j,d]   (scaled by p_rel*0.25)
// ---------------------------------------------------------------------------
__global__ void __launch_bounds__(256) prep_mats(
        const float* __restrict__ lin_w, const float* __restrict__ kw,
        const float* __restrict__ qw, const float* __restrict__ vw,
        const float* __restrict__ aw,
        const float* __restrict__ a_rel, const float* __restrict__ m_rel,
        const float* __restrict__ p_rel,
        const float* __restrict__ qb, const float* __restrict__ vb,
        __half* __restrict__ wth, float* __restrict__ tb)
{
    int b = blockIdx.x, tid = threadIdx.x;
    const int srcT[3] = {0, 0, 1}, dstT[3] = {0, 1, 0};
    __half2* dsth = (__half2*)(wth + (size_t)b * 16384);

    if (b < 10) {
        const float* W = (b < 2) ? lin_w + (size_t)b * 16384
                       : (b < 6) ? kw + (size_t)(b - 2) * 16384
                                 : aw + (size_t)(b - 6) * 16384;
        for (int i = tid; i < 8192; i += 256) {
            int reg = i & 1, lane = (i >> 1) & 31, ks = (i >> 6) & 7, nt = i >> 9;
            int k0 = ks * 16 + (lane & 3) * 2 + reg * 8;
            int n = nt * 8 + (lane >> 2);
            dsth[i] = __floats2half2_rn(__ldg(&W[k0 * 128 + n]),
                                        __ldg(&W[(k0 + 1) * 128 + n]));
        }
        return;
    }
    int c = b - 10, l = c / 6, idx = c % 6;
    int rel = (idx < 3) ? idx : (idx == 3 ? 0 : (idx == 4 ? 2 : 1));
    bool isQA = (idx >= 3);
    const float* W  = isQA ? qw + (size_t)(l * 2 + dstT[rel]) * 16384
                           : vw + (size_t)(l * 2 + srcT[rel]) * 16384;
    const float* T  = (isQA ? a_rel : m_rel) + (size_t)(l * 3 + rel) * 2048;
    const float* Bi = isQA ? qb + (l * 2 + dstT[rel]) * 128
                           : vb + (l * 2 + srcT[rel]) * 128;
    __shared__ float Ts[2048];
    __shared__ float sc[8];
    for (int i = tid; i < 2048; i += 256) Ts[i] = __ldg(&T[i]);
    if (tid < 8) sc[tid] = isQA ? __ldg(&p_rel[(l * 3 + rel) * 8 + tid]) * 0.25f : 1.f;
    __syncthreads();
    for (int i = tid; i < 8192; i += 256) {
        int reg = i & 1, lane = (i >> 1) & 31, ks = (i >> 6) & 7, nt = i >> 9;
        int k0 = ks * 16 + (lane & 3) * 2 + reg * 8;
        int n = nt * 8 + (lane >> 2);
        int h = n >> 4, j = n & 15;
        float s0 = 0.f, s1 = 0.f;
        if (isQA) {
#pragma unroll
            for (int d = 0; d < 16; ++d) {
                float t = Ts[h * 256 + j * 16 + d];
                s0 += __ldg(&W[k0 * 128 + h * 16 + d]) * t;
                s1 += __ldg(&W[(k0 + 1) * 128 + h * 16 + d]) * t;
            }
        } else {
#pragma unroll
            for (int d = 0; d < 16; ++d) {
                float t = Ts[h * 256 + d * 16 + j];
                s0 += __ldg(&W[k0 * 128 + h * 16 + d]) * t;
                s1 += __ldg(&W[(k0 + 1) * 128 + h * 16 + d]) * t;
            }
        }
        dsth[i] = __floats2half2_rn(s0 * sc[h], s1 * sc[h]);
    }
    if (tid < 128) {
        int h = tid >> 4, j = tid & 15;
        float s = 0.f;
        if (isQA) {
#pragma unroll
            for (int d = 0; d < 16; ++d)
                s += __ldg(&Bi[h * 16 + d]) * Ts[h * 256 + j * 16 + d];
        } else {
#pragma unroll
            for (int d = 0; d < 16; ++d)
                s += __ldg(&Bi[h * 16 + d]) * Ts[h * 256 + d * 16 + j];
        }
        tb[c * 128 + tid] = s * sc[h];
    }
}

// ---------------------------------------------------------------------------
// fp16 GEMM mainloop: 512 threads, 16 warps (4M x 4N), warp tile 32x32.
// ---------------------------------------------------------------------------
constexpr int TG_THR = 512;
constexpr int TG_SMEMH = 128 * 136 * 2;   // 34816 B

__device__ __forceinline__ void gemm_tile_h(
        const uint32_t* AshU, const uint32_t* __restrict__ Bfh,
        int warpM, int warpN, int lane, float acc[2][4][4])
{
#pragma unroll
    for (int mt = 0; mt < 2; ++mt)
#pragma unroll
        for (int nt = 0; nt < 4; ++nt)
#pragma unroll
            for (int i = 0; i < 4; ++i) acc[mt][nt][i] = 0.f;
#pragma unroll
    for (int ks = 0; ks < 8; ++ks) {
        uint2 bv[4];
#pragma unroll
        for (int nt = 0; nt < 4; ++nt) {
            int ntA = warpN * 4 + nt;
            bv[nt] = __ldg((const uint2*)Bfh + ((ntA * 8 + ks) * 32 + lane));
        }
        uint32_t a[2][4];
#pragma unroll
        for (int mt = 0; mt < 2; ++mt) {
            int rb = warpM * 32 + mt * 16 + (lane >> 2);
            int cb = ks * 8 + (lane & 3);
            a[mt][0] = AshU[rb * 68 + cb];
            a[mt][1] = AshU[(rb + 8) * 68 + cb];
            a[mt][2] = AshU[rb * 68 + cb + 4];
            a[mt][3] = AshU[(rb + 8) * 68 + cb + 4];
        }
#pragma unroll
        for (int nt = 0; nt < 4; ++nt)
#pragma unroll
            for (int mt = 0; mt < 2; ++mt)
                MMA_F16(acc[mt][nt], a[mt], bv[nt].x, bv[nt].y);
    }
}

// ---------------------------------------------------------------------------
// tgemm1: single-output fp16 GEMM, merged type grid, fp32 output.
// PRE: 1=tanh-gelu, 2=embed(mean+relu), 3=gelu(A + A2[stmt-only]).
// POST: 1=relu, 2=skip blend.
// ---------------------------------------------------------------------------
template<int PRE, int POST>
__global__ void __launch_bounds__(TG_THR, 2) tgemm1(
        const float* __restrict__ A, const float* __restrict__ A2,
        const int* __restrict__ tok_s, const int* __restrict__ tok_f,
        const float* __restrict__ emb,
        const uint32_t* __restrict__ B0, const uint32_t* __restrict__ B1,
        const float* __restrict__ b0, const float* __restrict__ b1,
        const float* __restrict__ Xold,
        const float* __restrict__ skip0, const float* __restrict__ skip1,
        float* __restrict__ Out)
{
    extern __shared__ float sm[];
    uint32_t* AshU = (uint32_t*)sm;
    __half2* Ash2 = (__half2*)sm;
    int tid = threadIdx.x, wid = tid >> 5, lane = tid & 31;
    int warpM = wid & 3, warpN = wid >> 2;
    int b = blockIdx.x;
    bool tf = (b >= kGridS);
    int rowBase = tf ? (kNStmt + (b - kGridS) * 128) : b * 128;
    int Nend = tf ? kNTot : kNStmt;
    const uint32_t* Bf = tf ? B1 : B0;
    const float* bs = tf ? b1 : b0;

#pragma unroll 2
    for (int p = 0; p < 8; ++p) {
        int idx = p * TG_THR + tid;
        int r = idx >> 5, c4 = idx & 31;
        int n = rowBase + r;
        float4 v = make_float4(0.f, 0.f, 0.f, 0.f);
        if (n < Nend) {
            if (PRE == 2) {
                const int* tok = tf ? tok_f + (size_t)(n - kNStmt) * 16
                                    : tok_s + (size_t)n * 16;
#pragma unroll
                for (int i = 0; i < 16; ++i) {
                    int t = __ldg(&tok[i]);
                    float4 e4 = __ldg((const float4*)(emb + (size_t)t * 128) + c4);
                    v.x += e4.x; v.y += e4.y; v.z += e4.z; v.w += e4.w;
                }
                v.x = fmaxf(v.x * (1.f / 16.f), 0.f);
                v.y = fmaxf(v.y * (1.f / 16.f), 0.f);
                v.z = fmaxf(v.z * (1.f / 16.f), 0.f);
                v.w = fmaxf(v.w * (1.f / 16.f), 0.f);
            } else {
                v = __ldg((const float4*)(A + (size_t)n * 128 + c4 * 4));
                if (PRE == 3 && !tf) {
                    float4 w = __ldg((const float4*)(A2 + (size_t)n * 128 + c4 * 4));
                    v.x += w.x; v.y += w.y; v.z += w.z; v.w += w.w;
                }
                if (PRE == 1 || PRE == 3) {
                    v.x = gelu_t(v.x); v.y = gelu_t(v.y);
                    v.z = gelu_t(v.z); v.w = gelu_t(v.w);
                }
            }
        }
        Ash2[r * 68 + c4 * 2]     = __floats2half2_rn(v.x, v.y);
        Ash2[r * 68 + c4 * 2 + 1] = __floats2half2_rn(v.z, v.w);
    }
    __syncthreads();

    float gate = 1.f, og = 0.f;
    if (POST == 2) {
        float sv = __ldg(tf ? skip1 : skip0);
        gate = 1.f / (1.f + expf(-sv));
        og = 1.f - gate;
    }

    float acc[2][4][4];
    gemm_tile_h(AshU, Bf, warpM, warpN, lane, acc);

    int g = lane >> 2, t2 = (lane & 3) * 2;
#pragma unroll
    for (int mt = 0; mt < 2; ++mt) {
        int r0 = rowBase + warpM * 32 + mt * 16 + g;
#pragma unroll
        for (int nt = 0; nt < 4; ++nt) {
            int col = warpN * 32 + nt * 8 + t2;
            float bb0 = __ldg(&bs[col]), bb1 = __ldg(&bs[col + 1]);
            float o0 = acc[mt][nt][0] + bb0, o1 = acc[mt][nt][1] + bb1;
            float o2 = acc[mt][nt][2] + bb0, o3 = acc[mt][nt][3] + bb1;
            if (POST == 1) {
                o0 = fmaxf(o0, 0.f); o1 = fmaxf(o1, 0.f);
                o2 = fmaxf(o2, 0.f); o3 = fmaxf(o3, 0.f);
            }
            if (POST == 2) {
                if (r0 < Nend) {
                    float2 x = *(const float2*)(Xold + (size_t)r0 * 128 + col);
                    o0 = gate * o0 + og * x.x; o1 = gate * o1 + og * x.y;
                }
                if (r0 + 8 < Nend) {
                    float2 x = *(const float2*)(Xold + (size_t)(r0 + 8) * 128 + col);
                    o2 = gate * o2 + og * x.x; o3 = gate * o3 + og * x.y;
                }
            }
            if (r0 < Nend)
                *(float2*)(Out + (size_t)r0 * 128 + col) = make_float2(o0, o1);
            if (r0 + 8 < Nend)
                *(float2*)(Out + (size_t)(r0 + 8) * 128 + col) = make_float2(o2, o3);
        }
    }
}

// ---------------------------------------------------------------------------
// tgemm_kqv: 5 outputs. j: 0=k(h16) 1=vA(h16) 2=vB(h16,stmt) 3=qa(f32) 4=qa2(f32,stmt)
// ---------------------------------------------------------------------------
struct KqvP {
    const uint32_t* B[2][5];
    const float*    bs[2][5];
};

__global__ void __launch_bounds__(TG_THR, 2) tgemm_kqv(
        const float* __restrict__ A, KqvP P,
        __half* __restrict__ Ok, __half* __restrict__ OvA, __half* __restrict__ OvB,
        float* __restrict__ Oqa, float* __restrict__ Oqa2)
{
    extern __shared__ float sm[];
    uint32_t* AshU = (uint32_t*)sm;
    __half2* Ash2 = (__half2*)sm;
    int tid = threadIdx.x, wid = tid >> 5, lane = tid & 31;
    int warpM = wid & 3, warpN = wid >> 2;
    int b = blockIdx.x;
    bool tf = (b >= kGridS);
    int rowBase = tf ? (kNStmt + (b - kGridS) * 128) : b * 128;
    int Nend = tf ? kNTot : kNStmt;
    int ti = tf ? 1 : 0;

#pragma unroll 4
    for (int p = 0; p < 8; ++p) {
        int idx = p * TG_THR + tid;
        int r = idx >> 5, c4 = idx & 31;
        int n = rowBase + r;
        float4 v = make_float4(0.f, 0.f, 0.f, 0.f);
        if (n < Nend) v = __ldg((const float4*)(A + (size_t)n * 128 + c4 * 4));
        Ash2[r * 68 + c4 * 2]     = __floats2half2_rn(v.x, v.y);
        Ash2[r * 68 + c4 * 2 + 1] = __floats2half2_rn(v.z, v.w);
    }
    __syncthreads();

    int g = lane >> 2, t2 = (lane & 3) * 2;
#pragma unroll
    for (int j = 0; j < 5; ++j) {
        if (tf && (j == 2 || j == 4)) continue;
        float acc[2][4][4];
        gemm_tile_h(AshU, P.B[ti][j], warpM, warpN, lane, acc);
        const float* bs = P.bs[ti][j];
#pragma unroll
        for (int mt = 0; mt < 2; ++mt) {
            int r0 = rowBase + warpM * 32 + mt * 16 + g;
#pragma unroll
            for (int nt = 0; nt < 4; ++nt) {
                int col = warpN * 32 + nt * 8 + t2;
                float bb0 = __ldg(&bs[col]), bb1 = __ldg(&bs[col + 1]);
                float o0 = acc[mt][nt][0] + bb0, o1 = acc[mt][nt][1] + bb1;
                float o2 = acc[mt][nt][2] + bb0, o3 = acc[mt][nt][3] + bb1;
                if (j < 3) {
                    __half* Oh = (j == 0) ? Ok : (j == 1) ? OvA : OvB;
                    if (r0 < Nend)
                        *(__half2*)(Oh + (size_t)r0 * 128 + col) = __floats2half2_rn(o0, o1);
                    if (r0 + 8 < Nend)
                        *(__half2*)(Oh + (size_t)(r0 + 8) * 128 + col) = __floats2half2_rn(o2, o3);
                } else {
                    float* Of = (j == 3) ? Oqa : Oqa2;
                    if (r0 < Nend)
                        *(float2*)(Of + (size_t)r0 * 128 + col) = make_float2(o0, o1);
                    if (r0 + 8 < Nend)
                        *(float2*)(Of + (size_t)(r0 + 8) * 128 + col) = make_float2(o2, o3);
                }
            }
        }
    }
}

// ---------------------------------------------------------------------------
// CSR build
// ---------------------------------------------------------------------------
__global__ void zero_int(int* __restrict__ p, int n) {
    int i = blockIdx.x * 256 + threadIdx.x;
    if (i < n) p[i] = 0;
}

__global__ void hist3(const int* __restrict__ d0, const int* __restrict__ d1,
                      const int* __restrict__ d2, int* __restrict__ cnt) {
    int r = blockIdx.y;
    const int* dst = (r == 0) ? d0 : (r == 1) ? d1 : d2;
    int off = (r == 0) ? 0 : (r == 1) ? kNStmt : kNStmt + kNFunc;
    int i = blockIdx.x * 256 + threadIdx.x;
    if (i < kE) atomicAdd(&cnt[off + __ldg(&dst[i])], 1);
}

__global__ void __launch_bounds__(1024) exscan3(const int* __restrict__ cnt,
                                                int* __restrict__ starts) {
    __shared__ int wsum[32];
    __shared__ int carry_s;
    const int cntOff[3] = {0, kNStmt, kNStmt + kNFunc};
    const int stOff[3]  = {0, kNStmt + 1, kNStmt + kNFunc + 2};
    const int ns[3]     = {kNStmt, kNFunc, kNStmt};
    int r = blockIdx.x;
    const int* c = cnt + cntOff[r];
    int* st = starts + stOff[r];
    int n = ns[r];
    int tid = threadIdx.x, lane = tid & 31, w = tid >> 5;
    if (tid == 0) carry_s = 0;
    __syncthreads();
    for (int base = 0; base < n; base += 1024) {
        int i = base + tid;
        int v = (i < n) ? c[i] : 0;
        int x = v;
#pragma unroll
        for (int o = 1; o < 32; o <<= 1) {
            int t = __shfl_up_sync(0xffffffffu, x, o);
            if (lane >= o) x += t;
        }
        if (lane == 31) wsum[w] = x;
        __syncthreads();
        if (w == 0) {
            int y = wsum[lane];
#pragma unroll
            for (int o = 1; o < 32; o <<= 1) {
                int t = __shfl_up_sync(0xffffffffu, y, o);
                if (lane >= o) y += t;
            }
            wsum[lane] = y;
        }
        __syncthreads();
        int incl = x + (w > 0 ? wsum[w - 1] : 0);
        int carry = carry_s;
        if (i < n) st[i] = carry + incl - v;
        __syncthreads();
        if (tid == 0) carry_s = carry + wsum[31];
        __syncthreads();
    }
    if (tid == 0) st[n] = carry_s;
}

__global__ void scat3(const int* __restrict__ s0, const int* __restrict__ d0,
                      const int* __restrict__ s1, const int* __restrict__ d1,
                      const int* __restrict__ s2, const int* __restrict__ d2,
                      const int* __restrict__ starts, int* __restrict__ cur,
                      int* __restrict__ out) {
    int r = blockIdx.y;
    const int* src = (r == 0) ? s0 : (r == 1) ? s1 : s2;
    const int* dst = (r == 0) ? d0 : (r == 1) ? d1 : d2;
    int cOff = (r == 0) ? 0 : (r == 1) ? kNStmt : kNStmt + kNFunc;
    int sOff = (r == 0) ? 0 : (r == 1) ? kNStmt + 1 : kNStmt + kNFunc + 2;
    int i = blockIdx.x * 256 + threadIdx.x;
    if (i < kE) {
        int d = __ldg(&dst[i]);
        int pos = __ldg(&starts[sOff + d]) + atomicAdd(&cur[cOff + d], 1);
        out[(size_t)r * kE + pos] = __ldg(&src[i]);
    }
}

// ---------------------------------------------------------------------------
// Attention: warp per (dst, relation) chain. lane = h*4+quarter, uint2 loads.
// ---------------------------------------------------------------------------
__device__ __forceinline__ float4 attn_edges(
        int e0, int e1, int lane, float4 qa,
        const int* __restrict__ srcs,
        const __half* __restrict__ kb, const __half* __restrict__ vb)
{
    float m = -INFINITY, s = 0.f;
    float4 acc = make_float4(0.f, 0.f, 0.f, 0.f);
    if (e0 < e1) {
        int src = __ldg(&srcs[e0]);
        uint2 uk = __ldg((const uint2*)(kb + (size_t)src * 128) + lane);
        uint2 uv = __ldg((const uint2*)(vb + (size_t)src * 128) + lane);
        for (int e = e0; ; ) {
            int ne = e + 1;
            bool more = ne < e1;
            uint2 nuk, nuv;
            if (more) {
                int nsrc = __ldg(&srcs[ne]);
                nuk = __ldg((const uint2*)(kb + (size_t)nsrc * 128) + lane);
                nuv = __ldg((const uint2*)(vb + (size_t)nsrc * 128) + lane);
            }
            float2 k01 = __half22float2(*(__half2*)&uk.x);
            float2 k23 = __half22float2(*(__half2*)&uk.y);
            float2 v01 = __half22float2(*(__half2*)&uv.x);
            float2 v23 = __half22float2(*(__half2*)&uv.y);
            float lg = qa.x * k01.x + qa.y * k01.y + qa.z * k23.x + qa.w * k23.y;
            lg += __shfl_xor_sync(0xffffffffu, lg, 1);
            lg += __shfl_xor_sync(0xffffffffu, lg, 2);
            float nm = fmaxf(m, lg);
            float corr = __expf(m - nm);
            float p = __expf(lg - nm);
            s = s * corr + p;
            acc.x = acc.x * corr + p * v01.x;
            acc.y = acc.y * corr + p * v01.y;
            acc.z = acc.z * corr + p * v23.x;
            acc.w = acc.w * corr + p * v23.y;
            m = nm;
            if (!more) break;
            e = ne; uk = nuk; uv = nuv;
        }
    }
    float inv = 1.f / (s + 1e-16f);
    return make_float4(acc.x * inv, acc.y * inv, acc.z * inv, acc.w * inv);
}

constexpr int kBlkR0 = kNStmt / 8;   // 12500: stmt rel0
constexpr int kBlkR2 = kNStmt / 8;   // 12500: stmt rel2
constexpr int kBlkR1 = kNFunc / 8;   //  6250: func rel1

__global__ void __launch_bounds__(256) attn_all(
        const float* __restrict__ qa, const float* __restrict__ qa2,
        const __half* __restrict__ kh, const __half* __restrict__ vA,
        const __half* __restrict__ vB,
        const int* __restrict__ st, const int* __restrict__ srt,
        float* __restrict__ agg, float* __restrict__ agg2)
{
    int tid = threadIdx.x, wid = tid >> 5, lane = tid & 31;
    int b = blockIdx.x;
    if (b < kBlkR0) {                   // stmt, relation 0
        int dn = b * 8 + wid;
        float4 q0 = __ldg((const float4*)(qa + (size_t)dn * 128) + lane);
        float4 r = attn_edges(__ldg(&st[dn]), __ldg(&st[dn + 1]), lane, q0,
                              srt, kh, vA);
        ((float4*)(agg + (size_t)dn * 128))[lane] = r;
    } else if (b < kBlkR0 + kBlkR2) {   // stmt, relation 2 (func sources)
        int dn = (b - kBlkR0) * 8 + wid;
        const int* st2 = st + (kNStmt + kNFunc + 2);
        float4 q2 = __ldg((const float4*)(qa2 + (size_t)dn * 128) + lane);
        float4 r = attn_edges(__ldg(&st2[dn]), __ldg(&st2[dn + 1]), lane, q2,
                              srt + 2 * kE,
                              kh + (size_t)kNStmt * 128, vA + (size_t)kNStmt * 128);
        ((float4*)(agg2 + (size_t)dn * 128))[lane] = r;
    } else {                            // func, relation 1
        int dn = (b - kBlkR0 - kBlkR2) * 8 + wid;
        const int* st1 = st + (kNStmt + 1);
        float4 q1 = __ldg((const float4*)(qa + (size_t)(kNStmt + dn) * 128) + lane);
        float4 r = attn_edges(__ldg(&st1[dn]), __ldg(&st1[dn + 1]), lane, q1,
                              srt + kE, kh, vB);
        ((float4*)(agg + (size_t)(kNStmt + dn) * 128))[lane] = r;
    }
}

// ---------------------------------------------------------------------------
// Orchestration
// ---------------------------------------------------------------------------
extern "C" void kernel_launch(void* const* d_in, const int* in_sizes, int n_in,
                              void* d_out, int out_size) {
    const int* tok_s = (const int*)d_in[0];
    const int* tok_f = (const int*)d_in[1];
    const int* e0s = (const int*)d_in[2], *e0d = (const int*)d_in[3];
    const int* e1s = (const int*)d_in[4], *e1d = (const int*)d_in[5];
    const int* e2s = (const int*)d_in[6], *e2d = (const int*)d_in[7];
    const float* emb   = (const float*)d_in[8];
    const float* lin_w = (const float*)d_in[9];
    const float* lin_b = (const float*)d_in[10];
    const float* kw = (const float*)d_in[11];
    const float* kb = (const float*)d_in[12];
    const float* qw = (const float*)d_in[13];
    const float* qb = (const float*)d_in[14];
    const float* vw = (const float*)d_in[15];
    const float* vb = (const float*)d_in[16];
    const float* aw = (const float*)d_in[17];
    const float* ab = (const float*)d_in[18];
    const float* skip  = (const float*)d_in[19];
    const float* a_rel = (const float*)d_in[20];
    const float* m_rel = (const float*)d_in[21];
    const float* p_rel = (const float*)d_in[22];
    float* out = (float*)d_out;

    float *px, *pqa, *pqa2, *pagg, *pagg2, *ptb;
    __half *pkh, *pvA, *pvB, *pwth;
    int *ptmp, *pst, *psrt;
    cudaGetSymbolAddress((void**)&px,    g_x);
    cudaGetSymbolAddress((void**)&pqa,   g_qa);
    cudaGetSymbolAddress((void**)&pqa2,  g_qa2);
    cudaGetSymbolAddress((void**)&pkh,   g_kh);
    cudaGetSymbolAddress((void**)&pvA,   g_vA);
    cudaGetSymbolAddress((void**)&pvB,   g_vB);
    cudaGetSymbolAddress((void**)&pagg,  g_agg);
    cudaGetSymbolAddress((void**)&pagg2, g_agg2);
    cudaGetSymbolAddress((void**)&pwth,  g_wth);
    cudaGetSymbolAddress((void**)&ptb,   g_tb);
    cudaGetSymbolAddress((void**)&ptmp,  g_tmp);
    cudaGetSymbolAddress((void**)&pst,   g_starts);
    cudaGetSymbolAddress((void**)&psrt,  g_srt);

    cudaFuncSetAttribute(tgemm1<2,1>, cudaFuncAttributeMaxDynamicSharedMemorySize, TG_SMEMH);
    cudaFuncSetAttribute(tgemm1<3,2>, cudaFuncAttributeMaxDynamicSharedMemorySize, TG_SMEMH);
    cudaFuncSetAttribute(tgemm_kqv, cudaFuncAttributeMaxDynamicSharedMemorySize, TG_SMEMH);

    int egrid = (kE + 255) / 256;

    // CSR build
    zero_int<<<(500000 + 255) / 256, 256>>>(ptmp, 500000);
    hist3<<<dim3(egrid, 3), 256>>>(e0d, e1d, e2d, ptmp);
    exscan3<<<3, 1024>>>(ptmp, pst);
    scat3<<<dim3(egrid, 3), 256>>>(e0s, e0d, e1s, e1d, e2s, e2d,
                                   pst, ptmp + 250000, psrt);

    // Weight prep, then input linear with fused embed
    prep_mats<<<22, 256>>>(lin_w, kw, qw, vw, aw, a_rel, m_rel, p_rel, qb, vb,
                           pwth, ptb);

    const uint32_t* W = (const uint32_t*)pwth;   // 8192 uint32 per matrix
    tgemm1<2,1><<<kGridAll, TG_THR, TG_SMEMH>>>(
        nullptr, nullptr, tok_s, tok_f, emb,
        W, W + 8192, lin_b, lin_b + 128,
        nullptr, nullptr, nullptr, px);

    for (int l = 0; l < kL; ++l) {
        int m0 = l * 2, m1 = l * 2 + 1;
        size_t fs = 10 + (size_t)l * 6;

        KqvP P;
        P.B[0][0] = W + (size_t)(2 + m0) * 8192;
        P.B[0][1] = W + (fs + 0) * 8192;
        P.B[0][2] = W + (fs + 1) * 8192;
        P.B[0][3] = W + (fs + 3) * 8192;
        P.B[0][4] = W + (fs + 4) * 8192;
        P.bs[0][0] = kb + m0 * 128;
        P.bs[0][1] = ptb + (l * 6 + 0) * 128;
        P.bs[0][2] = ptb + (l * 6 + 1) * 128;
        P.bs[0][3] = ptb + (l * 6 + 3) * 128;
        P.bs[0][4] = ptb + (l * 6 + 4) * 128;
        P.B[1][0] = W + (size_t)(2 + m1) * 8192;
        P.B[1][1] = W + (fs + 2) * 8192;
        P.B[1][2] = nullptr;
        P.B[1][3] = W + (fs + 5) * 8192;
        P.B[1][4] = nullptr;
        P.bs[1][0] = kb + m1 * 128;
        P.bs[1][1] = ptb + (l * 6 + 2) * 128;
        P.bs[1][2] = nullptr;
        P.bs[1][3] = ptb + (l * 6 + 5) * 128;
        P.bs[1][4] = nullptr;

        tgemm_kqv<<<kGridAll, TG_THR, TG_SMEMH>>>(px, P, pkh, pvA, pvB, pqa, pqa2);

        attn_all<<<kBlkR0 + kBlkR2 + kBlkR1, 256>>>(pqa, pqa2, pkh, pvA, pvB,
                                                    pst, psrt, pagg, pagg2);

        float* dst = (l == kL - 1) ? out : px;
        tgemm1<3,2><<<kGridAll, TG_THR, TG_SMEMH>>>(
            pagg, pagg2, nullptr, nullptr, nullptr,
            W + (size_t)(6 + m0) * 8192, W + (size_t)(6 + m1) * 8192,
            ab + m0 * 128, ab + m1 * 128,
            px, skip + m0, skip + m1, dst);
    }
}